// round 11
// baseline (speedup 1.0000x reference)
#include <cuda_runtime.h>
#include <cstdint>

#define RCUT 5.2f
#define WPB 2
#define SEG_CAP 288                // 255 valid + up to 7 pads x 4 segments
#define NK (-23.083120654223414f)  // -eta/ln2, eta=16
#define PI_RC 0.604152403831652f   // pi / 5.2

__device__ __forceinline__ float ex2_approx(float x) {
    float r; asm("ex2.approx.f32 %0, %1;" : "=f"(r) : "f"(x)); return r;
}
__device__ __forceinline__ float cos_approx(float x) {
    float r; asm("cos.approx.f32 %0, %1;" : "=f"(r) : "f"(x)); return r;
}
__device__ __forceinline__ uint64_t pack2(float lo, float hi) {
    uint64_t r; asm("mov.b64 %0, {%1, %2};" : "=l"(r) : "f"(lo), "f"(hi)); return r;
}
__device__ __forceinline__ void unpack2(uint64_t v, float& lo, float& hi) {
    asm("mov.b64 {%0, %1}, %2;" : "=f"(lo), "=f"(hi) : "l"(v));
}
// Packed dual-FMA (SASS FFMA2) — only reachable via PTX fma.rn.f32x2.
__device__ __forceinline__ uint64_t fma2(uint64_t a, uint64_t b, uint64_t c) {
    uint64_t r; asm("fma.rn.f32x2 %0, %1, %2, %3;" : "=l"(r) : "l"(a), "l"(b), "l"(c));
    return r;
}

// Sum one species segment; len is a multiple of 8 (padded with fc=0 entries).
// SoA layout. Lanes 0-15 take elements kk..kk+3; lanes 16-31 take kk+4..kk+7.
__device__ __forceinline__ float seg_accum(const float* __restrict__ ds,
                                           const float* __restrict__ fcs,
                                           int len, int off4,
                                           uint64_t NK2, uint64_t A2, uint64_t C2) {
    uint64_t acc01 = 0ull, acc23 = 0ull;        // packed (0.0f, 0.0f)
    for (int kk = 0; kk < len; kk += 8) {
        float4 d4 = *(const float4*)(ds  + kk + off4);
        float4 f4 = *(const float4*)(fcs + kk + off4);
        uint64_t d01 = pack2(d4.x, d4.y), d23 = pack2(d4.z, d4.w);
        uint64_t y01 = fma2(fma2(NK2, d01, A2), d01, C2);
        uint64_t y23 = fma2(fma2(NK2, d23, A2), d23, C2);
        float y0, y1, y2, y3;
        unpack2(y01, y0, y1); unpack2(y23, y2, y3);
        uint64_t e01 = pack2(ex2_approx(y0), ex2_approx(y1));
        uint64_t e23 = pack2(ex2_approx(y2), ex2_approx(y3));
        acc01 = fma2(e01, pack2(f4.x, f4.y), acc01);
        acc23 = fma2(e23, pack2(f4.z, f4.w), acc23);
    }
    float a, b, c, d;
    unpack2(acc01, a, b); unpack2(acc23, c, d);
    return (a + b) + (c + d);
}

// Fast path: N == 256.
__global__ __launch_bounds__(32 * WPB, 24)
void radial_aev_256(const float* __restrict__ dmat,
                    const int*   __restrict__ species,
                    float*       __restrict__ out)
{
    __shared__ alignas(16) float s_d [WPB][SEG_CAP];
    __shared__ alignas(16) float s_fc[WPB][SEG_CAP];
    __shared__ uint32_t ssp[64];   // packed bytes: ((species-1)<<4) per j

    const int warp = threadIdx.x >> 5;
    const int lane = threadIdx.x & 31;
    const int row  = blockIdx.x * WPB + warp;
    const int brow = (blockIdx.x * WPB) >> 8;   // same batch for whole block

    // ---- block-cooperative species preprocess (64 threads = whole row) ----
    {
        int4 sv = ((const int4*)(species + (size_t)brow * 256))[threadIdx.x];
        uint32_t w =  (uint32_t)((sv.x - 1) << 4)
                   | ((uint32_t)((sv.y - 1) << 4) << 8)
                   | ((uint32_t)((sv.z - 1) << 4) << 16)
                   | ((uint32_t)((sv.w - 1) << 4) << 24);
        ssp[threadIdx.x] = w;
    }
    __syncthreads();

    // ---- Phase 1: lane owns j = 8*lane .. 8*lane+7 ----
    const float* __restrict__ drow = dmat + (size_t)row * 256;
    float4 a = ((const float4*)drow)[lane * 2];
    float4 b = ((const float4*)drow)[lane * 2 + 1];
    float dv[8] = {a.x, a.y, a.z, a.w, b.x, b.y, b.z, b.w};

    const uint32_t u0 = ssp[lane * 2], u1 = ssp[lane * 2 + 1];

    // validity (0<d<RC  <=>  d*(RC-d)>0) + packed 8-bit per-species counts
    int vvi[8];
    uint32_t cpk = 0;
    #pragma unroll
    for (int e = 0; e < 8; e++) {
        int v = (dv[e] * (RCUT - dv[e]) > 0.0f) ? 1 : 0;
        vvi[e] = v;
        uint32_t uw = (e < 4) ? u0 : u1;
        int s16 = (uw >> (8 * (e & 3))) & 0xff;    // (sp-1)<<4
        cpk += (uint32_t)v << (s16 >> 1);          // shift in {0,8,16,24}
    }

    // single packed inclusive scan (8-bit fields, counts <= 255: no carry)
    uint32_t ipk = cpk;
    #pragma unroll
    for (int o = 1; o < 32; o <<= 1) {
        uint32_t n = __shfl_up_sync(0xffffffffu, ipk, o);
        if (lane >= o) ipk += n;
    }
    const uint32_t tot = __shfl_sync(0xffffffffu, ipk, 31);
    const uint32_t epk = ipk - cpk;                // exclusive, packed

    const int T0 = tot & 0xff, T1 = (tot >> 8) & 0xff;
    const int T2 = (tot >> 16) & 0xff, T3 = tot >> 24;
    const int L0 = (T0 + 7) & ~7, L1 = (T1 + 7) & ~7;
    const int L2 = (T2 + 7) & ~7, L3 = (T3 + 7) & ~7;
    const int B1 = L0, B2 = L0 + L1, B3 = L0 + L1 + L2;

    // packed 16-bit cursors with bases folded in
    uint32_t rlo = (epk & 0xff)                | ((B1 + ((epk >> 8)  & 0xff)) << 16);
    uint32_t rhi = (B2 + ((epk >> 16) & 0xff)) | ((B3 + (epk >> 24))          << 16);

    float* __restrict__ bd = s_d[warp];
    float* __restrict__ bf = s_fc[warp];
    #pragma unroll
    for (int e = 0; e < 8; e++) {
        float d  = dv[e];
        float fc = fmaf(cos_approx(d * PI_RC), 0.5f, 0.5f);
        uint32_t uw = (e < 4) ? u0 : u1;
        int s16 = (uw >> (8 * (e & 3))) & 0xff;
        int hi  = s16 & 32;
        int sh16 = s16 & 16;
        uint32_t rp = hi ? rhi : rlo;
        int pos = (rp >> sh16) & 0xffff;
        if (vvi[e]) { bd[pos] = d; bf[pos] = fc; }
        uint32_t inc = (uint32_t)vvi[e] << sh16;
        rlo += hi ? 0u : inc;                       // SEL, no branch
        rhi += hi ? inc : 0u;
    }
    __syncwarp();

    // pad tails: lane -> (segment = lane>>3, k = lane&7), predicated stores
    {
        int s = lane >> 3, k = lane & 7;
        int Ts = (tot >> (8 * s)) & 0xff;
        int Bs = (s == 0) ? 0 : (s == 1) ? B1 : (s == 2) ? B2 : B3;
        int Ls = (Ts + 7) & ~7;
        if (Ts + k < Ls) { bd[Bs + Ts + k] = 1.0f; bf[Bs + Ts + k] = 0.0f; }
    }
    __syncwarp();

    // ---- Phase 2: lane = (p = lane&15, quad-half = lane>>4) ----
    const float shf = fmaf((float)(lane & 15), 0.26875f, 0.9f);
    const float A   = -2.0f * NK * shf;
    const float C   = NK * shf * shf;
    const uint64_t NK2 = pack2(NK, NK);
    const uint64_t A2  = pack2(A, A);
    const uint64_t C2  = pack2(C, C);
    const int off4 = (lane >> 4) << 2;

    float acc0 = seg_accum(bd,      bf,      L0, off4, NK2, A2, C2);
    float acc1 = seg_accum(bd + B1, bf + B1, L1, off4, NK2, A2, C2);
    float acc2 = seg_accum(bd + B2, bf + B2, L2, off4, NK2, A2, C2);
    float acc3 = seg_accum(bd + B3, bf + B3, L3, off4, NK2, A2, C2);

    acc0 += __shfl_xor_sync(0xffffffffu, acc0, 16);
    acc1 += __shfl_xor_sync(0xffffffffu, acc1, 16);
    acc2 += __shfl_xor_sync(0xffffffffu, acc2, 16);
    acc3 += __shfl_xor_sync(0xffffffffu, acc3, 16);

    // all 32 lanes store: lanes 0-15 write s0/s1, lanes 16-31 write s2/s3
    {
        float* orow = out + (size_t)row * 64;
        int  l15  = lane & 15;
        bool lo16 = lane < 16;
        int  off  = lo16 ? l15 : (32 + l15);
        orow[off]      = lo16 ? acc0 : acc2;
        orow[off + 16] = lo16 ? acc1 : acc3;
    }
}

// Generic fallback (any N): one 64-thread block per row, direct evaluation.
__global__ void radial_aev_generic(const float* __restrict__ dmat,
                                   const int*   __restrict__ species,
                                   float*       __restrict__ out,
                                   int N, int rows)
{
    int row = blockIdx.x;
    if (row >= rows) return;
    int t = threadIdx.x;            // 64 threads: s = t>>4, p = t&15
    int s = t >> 4, p = t & 15;
    float shf = fmaf((float)p, 0.26875f, 0.9f);
    const float* drow = dmat + (size_t)row * N;
    const int*   srow = species + (size_t)(row / N) * N;
    float acc = 0.0f;
    for (int j = 0; j < N; j++) {
        float d = drow[j];
        if (d > 0.0f && d < RCUT && (srow[j] - 1) == s) {
            float fc = 0.5f * __cosf(d * PI_RC) + 0.5f;
            float tt = d - shf;
            acc += __expf(-16.0f * tt * tt) * fc;
        }
    }
    out[(size_t)row * 64 + t] = acc;
}

extern "C" void kernel_launch(void* const* d_in, const int* in_sizes, int n_in,
                              void* d_out, int out_size)
{
    const float* dmat    = (const float*)d_in[0];
    const int*   species = (const int*)d_in[1];
    float*       out     = (float*)d_out;

    const int rows = in_sizes[1];                 // B*N
    const int N    = in_sizes[0] / in_sizes[1];   // N

    if (N == 256 && (rows & (WPB - 1)) == 0 && (rows & 255) == 0) {
        radial_aev_256<<<rows / WPB, 32 * WPB>>>(dmat, species, out);
    } else {
        radial_aev_generic<<<rows, 64>>>(dmat, species, out, N, rows);
    }
}